// round 4
// baseline (speedup 1.0000x reference)
#include <cuda_runtime.h>
#include <math.h>

#define SIZE_ 1024
#define HEADS 16
#define HD    64
#define SEQ   2048
#define BATCH 2
#define M_TOT (BATCH * SEQ)   // 4096

// Scratch (allocation-free): projected Q/K/V and attention context, all
// stored [B*S, SIZE] row-major (heads packed along the feature dim).
__device__ float g_qh[M_TOT * SIZE_];
__device__ float g_kh[M_TOT * SIZE_];
__device__ float g_vh[M_TOT * SIZE_];
__device__ float g_ctx[M_TOT * SIZE_];

// ----------------------------------------------------------------------------
// GEMM: C[m][n] = scale * (sum_k A[m][k] * W[n][k] + bias[n])
// A: [M,K] row-major, W: [N,K] row-major (so this is A @ W^T + b).
// Tiles: 64(M) x 64(N), K-step 32, 256 threads, 4x4 register tile per thread.
// Smem fragments stored transposed ([k][m]) so each thread reads one float4
// per operand per k — LDS phases ~3 per k vs 4 FMA issue cycles: compute bound.
// ----------------------------------------------------------------------------
__global__ void gemm_bias_kernel(const float* __restrict__ A,
                                 const float* __restrict__ W,
                                 const float* __restrict__ bias,
                                 float* __restrict__ C,
                                 float scale, int M, int N, int K) {
    __shared__ __align__(16) float As[32][68];
    __shared__ __align__(16) float Ws[32][68];

    const int t  = threadIdx.x;
    const int tx = t & 15;          // N sub-tile
    const int ty = t >> 4;          // M sub-tile
    const int m0 = blockIdx.y * 64;
    const int n0 = blockIdx.x * 64;

    float acc[4][4] = {};

    for (int k0 = 0; k0 < K; k0 += 32) {
        // Load A tile 64x32 (512 float4, 2 per thread), store transposed.
        #pragma unroll
        for (int e = 0; e < 2; e++) {
            int fi  = e * 256 + t;
            int row = fi >> 3;          // 0..63 (m within tile)
            int kq  = fi & 7;           // float4 index within 32 k
            float4 v = *(const float4*)&A[(size_t)(m0 + row) * K + k0 + kq * 4];
            As[kq * 4 + 0][row] = v.x;
            As[kq * 4 + 1][row] = v.y;
            As[kq * 4 + 2][row] = v.z;
            As[kq * 4 + 3][row] = v.w;
        }
        // Load W tile 64x32, store transposed.
        #pragma unroll
        for (int e = 0; e < 2; e++) {
            int fi  = e * 256 + t;
            int row = fi >> 3;          // n within tile
            int kq  = fi & 7;
            float4 v = *(const float4*)&W[(size_t)(n0 + row) * K + k0 + kq * 4];
            Ws[kq * 4 + 0][row] = v.x;
            Ws[kq * 4 + 1][row] = v.y;
            Ws[kq * 4 + 2][row] = v.z;
            Ws[kq * 4 + 3][row] = v.w;
        }
        __syncthreads();

        #pragma unroll
        for (int kk = 0; kk < 32; kk++) {
            float4 a = *(const float4*)&As[kk][ty * 4];
            float4 b = *(const float4*)&Ws[kk][tx * 4];
            float av[4] = {a.x, a.y, a.z, a.w};
            float bv[4] = {b.x, b.y, b.z, b.w};
            #pragma unroll
            for (int i = 0; i < 4; i++)
                #pragma unroll
                for (int j = 0; j < 4; j++)
                    acc[i][j] += av[i] * bv[j];
        }
        __syncthreads();
    }

    #pragma unroll
    for (int j = 0; j < 4; j++) {
        float b = bias[n0 + tx * 4 + j];
        #pragma unroll
        for (int i = 0; i < 4; i++) {
            C[(size_t)(m0 + ty * 4 + i) * N + n0 + tx * 4 + j] =
                scale * (acc[i][j] + b);
        }
    }
}

// ----------------------------------------------------------------------------
// Flash attention: one block per (64-query tile, head, batch).
// Q pre-scaled by 1/sqrt(HD) (folded into the Q projection). Streams K/V in
// 64-row tiles with online softmax; fp32 accumulation throughout.
// Smem (dynamic, ~70KB): QT,KT transposed [d][row], V natural [row][d],
// P natural [qrow][kvcol], plus per-row m/l/rescale.
// ----------------------------------------------------------------------------
__global__ void attn_kernel(const float* __restrict__ qh,
                            const float* __restrict__ kh,
                            const float* __restrict__ vh,
                            float* __restrict__ ctx) {
    extern __shared__ float sm[];
    float* QT   = sm;                 // [64][68]  QT[d][r]
    float* KT   = QT + 64 * 68;       // [64][68]  KT[d][c]
    float* VS   = KT + 64 * 68;       // [64][68]  VS[kv][d]
    float* PS   = VS + 64 * 68;       // [64][68]  PS[r][kv]
    float* mrow = PS + 64 * 68;       // [64]
    float* lrow = mrow + 64;          // [64]
    float* frow = lrow + 64;          // [64]

    const int t  = threadIdx.x;
    const int tx = t & 15;            // output d-column group
    const int ty = t >> 4;            // query-row group
    const int q0 = blockIdx.x * 64;
    const int h  = blockIdx.y;
    const int b  = blockIdx.z;

    const float* qbase = qh + (size_t)b * SEQ * SIZE_ + (size_t)h * HD;
    const float* kbase = kh + (size_t)b * SEQ * SIZE_ + (size_t)h * HD;
    const float* vbase = vh + (size_t)b * SEQ * SIZE_ + (size_t)h * HD;

    // Load Q tile transposed.
    #pragma unroll
    for (int e = 0; e < 16; e++) {
        int lin = e * 256 + t;        // 0..4095
        int r = lin >> 6, d = lin & 63;
        QT[d * 68 + r] = qbase[(size_t)(q0 + r) * SIZE_ + d];
    }
    if (t < 64) { mrow[t] = -1e30f; lrow[t] = 0.f; }
    float acc[4][4] = {};
    __syncthreads();

    for (int kv0 = 0; kv0 < SEQ; kv0 += 64) {
        // Load K (transposed) and V (natural) tiles.
        #pragma unroll
        for (int e = 0; e < 16; e++) {
            int lin = e * 256 + t;
            int r = lin >> 6, d = lin & 63;
            KT[d * 68 + r] = kbase[(size_t)(kv0 + r) * SIZE_ + d];
            VS[r * 68 + d] = vbase[(size_t)(kv0 + r) * SIZE_ + d];
        }
        __syncthreads();

        // S = Q K^T (64x64)
        float sc[4][4] = {};
        #pragma unroll 16
        for (int d = 0; d < 64; d++) {
            float4 a  = *(const float4*)&QT[d * 68 + ty * 4];
            float4 bb = *(const float4*)&KT[d * 68 + tx * 4];
            float av[4] = {a.x, a.y, a.z, a.w};
            float bv[4] = {bb.x, bb.y, bb.z, bb.w};
            #pragma unroll
            for (int i = 0; i < 4; i++)
                #pragma unroll
                for (int j = 0; j < 4; j++)
                    sc[i][j] += av[i] * bv[j];
        }
        // Write scores (row-contiguous float4 stores: conflict-free).
        #pragma unroll
        for (int i = 0; i < 4; i++) {
            float4 v = make_float4(sc[i][0], sc[i][1], sc[i][2], sc[i][3]);
            *(float4*)&PS[(ty * 4 + i) * 68 + tx * 4] = v;
        }
        __syncthreads();

        // Online softmax, one thread per query row.
        if (t < 64) {
            float m_old = mrow[t];
            float mt = m_old;
            float* prow = &PS[t * 68];
            #pragma unroll 8
            for (int c = 0; c < 64; c++) mt = fmaxf(mt, prow[c]);
            float f  = __expf(m_old - mt);
            float ls = 0.f;
            #pragma unroll 8
            for (int c = 0; c < 64; c++) {
                float p = __expf(prow[c] - mt);
                prow[c] = p;
                ls += p;
            }
            mrow[t] = mt;
            lrow[t] = lrow[t] * f + ls;
            frow[t] = f;
        }
        __syncthreads();

        // Rescale running output, then O += P @ V.
        #pragma unroll
        for (int i = 0; i < 4; i++) {
            float f = frow[ty * 4 + i];
            #pragma unroll
            for (int j = 0; j < 4; j++) acc[i][j] *= f;
        }
        #pragma unroll 8
        for (int kk = 0; kk < 64; kk++) {
            float4 bb = *(const float4*)&VS[kk * 68 + tx * 4];
            float bv[4] = {bb.x, bb.y, bb.z, bb.w};
            float av[4];
            #pragma unroll
            for (int i = 0; i < 4; i++) av[i] = PS[(ty * 4 + i) * 68 + kk];
            #pragma unroll
            for (int i = 0; i < 4; i++)
                #pragma unroll
                for (int j = 0; j < 4; j++)
                    acc[i][j] += av[i] * bv[j];
        }
        __syncthreads();   // protect KT/VS/PS before next tile's loads
    }

    // Normalize and write context in [B,S,H*D] layout (== transpose+merge).
    float* cbase = ctx + (size_t)b * SEQ * SIZE_ + (size_t)h * HD;
    #pragma unroll
    for (int i = 0; i < 4; i++) {
        float inv = 1.f / lrow[ty * 4 + i];
        #pragma unroll
        for (int j = 0; j < 4; j++) {
            cbase[(size_t)(q0 + ty * 4 + i) * SIZE_ + tx * 4 + j] =
                acc[i][j] * inv;
        }
    }
}

// ----------------------------------------------------------------------------
// Host launch: 3 projections -> attention -> output projection.
// ----------------------------------------------------------------------------
extern "C" void kernel_launch(void* const* d_in, const int* in_sizes, int n_in,
                              void* d_out, int out_size) {
    const float* q  = (const float*)d_in[0];
    const float* k  = (const float*)d_in[1];
    const float* v  = (const float*)d_in[2];
    const float* Wq = (const float*)d_in[3];
    const float* bq = (const float*)d_in[4];
    const float* Wk = (const float*)d_in[5];
    const float* bk = (const float*)d_in[6];
    const float* Wv = (const float*)d_in[7];
    const float* bv = (const float*)d_in[8];
    const float* Wo = (const float*)d_in[9];
    const float* bo = (const float*)d_in[10];
    float* out = (float*)d_out;

    float *qh, *kh, *vh, *ctx;
    cudaGetSymbolAddress((void**)&qh,  g_qh);
    cudaGetSymbolAddress((void**)&kh,  g_kh);
    cudaGetSymbolAddress((void**)&vh,  g_vh);
    cudaGetSymbolAddress((void**)&ctx, g_ctx);

    const dim3 gb(SIZE_ / 64, M_TOT / 64);   // (16, 64)
    const float qscale = 0.125f;             // 1/sqrt(HD)

    gemm_bias_kernel<<<gb, 256>>>(q, Wq, bq, qh, qscale, M_TOT, SIZE_, SIZE_);
    gemm_bias_kernel<<<gb, 256>>>(k, Wk, bk, kh, 1.0f,   M_TOT, SIZE_, SIZE_);
    gemm_bias_kernel<<<gb, 256>>>(v, Wv, bv, vh, 1.0f,   M_TOT, SIZE_, SIZE_);

    const int smem_bytes = (4 * 64 * 68 + 3 * 64) * (int)sizeof(float); // ~70KB
    cudaFuncSetAttribute(attn_kernel,
                         cudaFuncAttributeMaxDynamicSharedMemorySize,
                         smem_bytes);
    attn_kernel<<<dim3(SEQ / 64, HEADS, BATCH), 256, smem_bytes>>>(qh, kh, vh, ctx);

    gemm_bias_kernel<<<gb, 256>>>(ctx, Wo, bo, out, 1.0f, M_TOT, SIZE_, SIZE_);
}

// round 6
// speedup vs baseline: 1.6148x; 1.6148x over previous
#include <cuda_runtime.h>
#include <cuda_bf16.h>
#include <cstdint>
#include <math.h>

#define SIZE_ 1024
#define HEADS 16
#define HD    64
#define SEQ   2048
#define BATCH 2
#define M_TOT (BATCH * SEQ)   // 4096

// Scratch (allocation-free)
__device__ float g_qh[M_TOT * SIZE_];
__device__ float g_kh[M_TOT * SIZE_];
__device__ float g_vh[M_TOT * SIZE_];
__device__ float g_ctx[M_TOT * SIZE_];

// ============================================================================
// Warp-level MMA helpers (base sm_103 ISA — no 'a' features)
// ============================================================================
__device__ __forceinline__ uint32_t smem_u32(const void* p) {
    uint32_t a;
    asm("{ .reg .u64 t; cvta.to.shared.u64 t, %1; cvt.u32.u64 %0, t; }"
        : "=r"(a) : "l"(p));
    return a;
}

__device__ __forceinline__ void ldm_x4(uint32_t* r, uint32_t addr) {
    asm volatile("ldmatrix.sync.aligned.m8n8.x4.shared.b16 {%0,%1,%2,%3}, [%4];"
                 : "=r"(r[0]), "=r"(r[1]), "=r"(r[2]), "=r"(r[3]) : "r"(addr));
}

// D += A * B  (m16n8k16, bf16 in, fp32 acc)
__device__ __forceinline__ void mma_bf16(float* c, const uint32_t* a,
                                         const uint32_t* b) {
    asm volatile(
        "mma.sync.aligned.m16n8k16.row.col.f32.bf16.bf16.f32 "
        "{%0,%1,%2,%3}, {%4,%5,%6,%7}, {%8,%9}, {%0,%1,%2,%3};"
        : "+f"(c[0]), "+f"(c[1]), "+f"(c[2]), "+f"(c[3])
        : "r"(a[0]), "r"(a[1]), "r"(a[2]), "r"(a[3]), "r"(b[0]), "r"(b[1]));
}

// fp32 -> bf16 hi + bf16 lo (3-term split source)
__device__ __forceinline__ void split4(float4 v, uint2& hi, uint2& lo) {
    __nv_bfloat162 h01 = __floats2bfloat162_rn(v.x, v.y);
    __nv_bfloat162 h23 = __floats2bfloat162_rn(v.z, v.w);
    __nv_bfloat162 l01 = __floats2bfloat162_rn(v.x - __low2float(h01),
                                               v.y - __high2float(h01));
    __nv_bfloat162 l23 = __floats2bfloat162_rn(v.z - __low2float(h23),
                                               v.w - __high2float(h23));
    hi.x = *(uint32_t*)&h01; hi.y = *(uint32_t*)&h23;
    lo.x = *(uint32_t*)&l01; lo.y = *(uint32_t*)&l23;
}

// ============================================================================
// Tensor-core GEMM: C[m][n] = scale * (sum_k A[m][k]*W[n][k] + bias[n])
// bf16 split: Ah*Bh + Ah*Bl + Al*Bh, fp32 register accumulators.
// CTA tile 128x128, K-chunk 32, 8 warps (2M x 4N -> warp tile 64x32).
// SMEM row stride 40 bf16 (80B): ldmatrix rows hit banks r*20%32 (distinct).
// ============================================================================
#define KC 32
#define NCHUNK (SIZE_ / KC)            // 32
#define ASTR 40                        // bf16 elems per smem row
#define TILEB (128 * ASTR * 2)         // 10240 B per tile
#define GEMM_SMEM (2 * 4 * TILEB)      // 81920 B (double buf x {Ah,Al,Bh,Bl})

__global__ __launch_bounds__(256, 1)
void gemm_tc_kernel(const float* __restrict__ A, const float* __restrict__ W,
                    const float* __restrict__ bias, float* __restrict__ C,
                    float scale) {
    extern __shared__ char smem[];
    const uint32_t sb = smem_u32(smem);
    const int t = threadIdx.x, wid = t >> 5, lane = t & 31;
    const int m0 = blockIdx.y * 128, n0 = blockIdx.x * 128;
    const int wm = (wid >> 2) * 64;    // warp M offset in tile
    const int wn = (wid & 3) * 32;     // warp N offset in tile

    // ldmatrix per-lane element offsets within a tile (see header comment):
    // A x4: j=lane>>3 -> (row += (j&1)*8, col += (j>>1)*8)
    // B x4: j        -> (row += (j>>1)*8, col += (j&1)*8)
    const int lr = lane & 7;
    const uint32_t aoff = (lr + ((lane >> 3) & 1) * 8) * ASTR + (lane >> 4) * 8;
    const uint32_t boff = (lr + (lane >> 4) * 8) * ASTR + ((lane >> 3) & 1) * 8;

    float acc[4][4][4] = {};           // [mt][nt][frag]
    float4 ga[4], gb[4];               // staged global loads

    auto gload = [&](int chunk) {
        const int k0 = chunk * KC;
        #pragma unroll
        for (int e = 0; e < 4; e++) {
            int fi = e * 256 + t;
            int r = fi >> 3, c4 = fi & 7;
            ga[e] = *(const float4*)&A[(size_t)(m0 + r) * SIZE_ + k0 + c4 * 4];
            gb[e] = *(const float4*)&W[(size_t)(n0 + r) * SIZE_ + k0 + c4 * 4];
        }
    };
    auto cstore = [&](int buf) {
        char* base = smem + buf * 4 * TILEB;
        #pragma unroll
        for (int e = 0; e < 4; e++) {
            int fi = e * 256 + t;
            int r = fi >> 3, c4 = fi & 7;
            uint32_t off = (uint32_t)(r * ASTR + c4 * 4) * 2;
            uint2 hi, lo;
            split4(ga[e], hi, lo);
            *(uint2*)(base + off)             = hi;   // Ahi
            *(uint2*)(base + TILEB + off)     = lo;   // Alo
            split4(gb[e], hi, lo);
            *(uint2*)(base + 2 * TILEB + off) = hi;   // Bhi
            *(uint2*)(base + 3 * TILEB + off) = lo;   // Blo
        }
    };
    auto compute = [&](int buf) {
        const uint32_t AhiB = sb + buf * 4 * TILEB;
        const uint32_t AloB = AhiB + TILEB;
        const uint32_t BhiB = AhiB + 2 * TILEB;
        const uint32_t BloB = AhiB + 3 * TILEB;
        #pragma unroll
        for (int ks = 0; ks < KC; ks += 16) {
            uint32_t Ah[4][4], Al[4][4], Bh[8], Bl[8];
            #pragma unroll
            for (int mt = 0; mt < 4; mt++) {
                uint32_t o = 2u * (aoff + (wm + mt * 16) * ASTR + ks);
                ldm_x4(Ah[mt], AhiB + o);
                ldm_x4(Al[mt], AloB + o);
            }
            #pragma unroll
            for (int n2 = 0; n2 < 2; n2++) {
                uint32_t o = 2u * (boff + (wn + n2 * 16) * ASTR + ks);
                ldm_x4(&Bh[n2 * 4], BhiB + o);
                ldm_x4(&Bl[n2 * 4], BloB + o);
            }
            #pragma unroll
            for (int mt = 0; mt < 4; mt++)
                #pragma unroll
                for (int nt = 0; nt < 4; nt++) {
                    const uint32_t* bh = &Bh[(nt >> 1) * 4 + (nt & 1) * 2];
                    const uint32_t* bl = &Bl[(nt >> 1) * 4 + (nt & 1) * 2];
                    mma_bf16(acc[mt][nt], Ah[mt], bh);
                    mma_bf16(acc[mt][nt], Ah[mt], bl);
                    mma_bf16(acc[mt][nt], Al[mt], bh);
                }
        }
    };

    gload(0);
    cstore(0);
    for (int i = 0; i < NCHUNK; i++) {
        __syncthreads();               // chunk i tiles visible; prev reads done
        if (i + 1 < NCHUNK) gload(i + 1);
        compute(i & 1);
        if (i + 1 < NCHUNK) cstore((i + 1) & 1);
    }

    // Epilogue: c-frag rows = lane>>2 (+8), cols = 2*(lane&3)+{0,1}
    const int gid = lane >> 2, tig = lane & 3;
    #pragma unroll
    for (int mt = 0; mt < 4; mt++) {
        #pragma unroll
        for (int nt = 0; nt < 4; nt++) {
            const int n = n0 + wn + nt * 8 + tig * 2;
            const int m = m0 + wm + mt * 16 + gid;
            float2 b01 = *(const float2*)&bias[n];
            float2 o0, o1;
            o0.x = scale * (acc[mt][nt][0] + b01.x);
            o0.y = scale * (acc[mt][nt][1] + b01.y);
            o1.x = scale * (acc[mt][nt][2] + b01.x);
            o1.y = scale * (acc[mt][nt][3] + b01.y);
            *(float2*)&C[(size_t)m * SIZE_ + n]       = o0;
            *(float2*)&C[(size_t)(m + 8) * SIZE_ + n] = o1;
        }
    }
}

// ----------------------------------------------------------------------------
// Flash attention (unchanged SIMT fp32): one block per (64-query tile, head, b)
// ----------------------------------------------------------------------------
__global__ void attn_kernel(const float* __restrict__ qh,
                            const float* __restrict__ kh,
                            const float* __restrict__ vh,
                            float* __restrict__ ctx) {
    extern __shared__ float sm[];
    float* QT   = sm;                 // [64][68]  QT[d][r]
    float* KT   = QT + 64 * 68;       // [64][68]  KT[d][c]
    float* VS   = KT + 64 * 68;       // [64][68]  VS[kv][d]
    float* PS   = VS + 64 * 68;       // [64][68]  PS[r][kv]
    float* mrow = PS + 64 * 68;
    float* lrow = mrow + 64;
    float* frow = lrow + 64;

    const int t  = threadIdx.x;
    const int tx = t & 15;
    const int ty = t >> 4;
    const int q0 = blockIdx.x * 64;
    const int h  = blockIdx.y;
    const int b  = blockIdx.z;

    const float* qbase = qh + (size_t)b * SEQ * SIZE_ + (size_t)h * HD;
    const float* kbase = kh + (size_t)b * SEQ * SIZE_ + (size_t)h * HD;
    const float* vbase = vh + (size_t)b * SEQ * SIZE_ + (size_t)h * HD;

    #pragma unroll
    for (int e = 0; e < 16; e++) {
        int lin = e * 256 + t;
        int r = lin >> 6, d = lin & 63;
        QT[d * 68 + r] = qbase[(size_t)(q0 + r) * SIZE_ + d];
    }
    if (t < 64) { mrow[t] = -1e30f; lrow[t] = 0.f; }
    float acc[4][4] = {};
    __syncthreads();

    for (int kv0 = 0; kv0 < SEQ; kv0 += 64) {
        #pragma unroll
        for (int e = 0; e < 16; e++) {
            int lin = e * 256 + t;
            int r = lin >> 6, d = lin & 63;
            KT[d * 68 + r] = kbase[(size_t)(kv0 + r) * SIZE_ + d];
            VS[r * 68 + d] = vbase[(size_t)(kv0 + r) * SIZE_ + d];
        }
        __syncthreads();

        float sc[4][4] = {};
        #pragma unroll 16
        for (int d = 0; d < 64; d++) {
            float4 a  = *(const float4*)&QT[d * 68 + ty * 4];
            float4 bb = *(const float4*)&KT[d * 68 + tx * 4];
            float av[4] = {a.x, a.y, a.z, a.w};
            float bv[4] = {bb.x, bb.y, bb.z, bb.w};
            #pragma unroll
            for (int i = 0; i < 4; i++)
                #pragma unroll
                for (int j = 0; j < 4; j++)
                    sc[i][j] += av[i] * bv[j];
        }
        #pragma unroll
        for (int i = 0; i < 4; i++) {
            float4 v = make_float4(sc[i][0], sc[i][1], sc[i][2], sc[i][3]);
            *(float4*)&PS[(ty * 4 + i) * 68 + tx * 4] = v;
        }
        __syncthreads();

        if (t < 64) {
            float m_old = mrow[t];
            float mt = m_old;
            float* prow = &PS[t * 68];
            #pragma unroll 8
            for (int c = 0; c < 64; c++) mt = fmaxf(mt, prow[c]);
            float f  = __expf(m_old - mt);
            float ls = 0.f;
            #pragma unroll 8
            for (int c = 0; c < 64; c++) {
                float p = __expf(prow[c] - mt);
                prow[c] = p;
                ls += p;
            }
            mrow[t] = mt;
            lrow[t] = lrow[t] * f + ls;
            frow[t] = f;
        }
        __syncthreads();

        #pragma unroll
        for (int i = 0; i < 4; i++) {
            float f = frow[ty * 4 + i];
            #pragma unroll
            for (int j = 0; j < 4; j++) acc[i][j] *= f;
        }
        #pragma unroll 8
        for (int kk = 0; kk < 64; kk++) {
            float4 bb = *(const float4*)&VS[kk * 68 + tx * 4];
            float bv[4] = {bb.x, bb.y, bb.z, bb.w};
            float av[4];
            #pragma unroll
            for (int i = 0; i < 4; i++) av[i] = PS[(ty * 4 + i) * 68 + kk];
            #pragma unroll
            for (int i = 0; i < 4; i++)
                #pragma unroll
                for (int j = 0; j < 4; j++)
                    acc[i][j] += av[i] * bv[j];
        }
        __syncthreads();
    }

    float* cbase = ctx + (size_t)b * SEQ * SIZE_ + (size_t)h * HD;
    #pragma unroll
    for (int i = 0; i < 4; i++) {
        float inv = 1.f / lrow[ty * 4 + i];
        #pragma unroll
        for (int j = 0; j < 4; j++) {
            cbase[(size_t)(q0 + ty * 4 + i) * SIZE_ + tx * 4 + j] =
                acc[i][j] * inv;
        }
    }
}

// ----------------------------------------------------------------------------
// Host launch
// ----------------------------------------------------------------------------
extern "C" void kernel_launch(void* const* d_in, const int* in_sizes, int n_in,
                              void* d_out, int out_size) {
    const float* q  = (const float*)d_in[0];
    const float* k  = (const float*)d_in[1];
    const float* v  = (const float*)d_in[2];
    const float* Wq = (const float*)d_in[3];
    const float* bq = (const float*)d_in[4];
    const float* Wk = (const float*)d_in[5];
    const float* bk = (const float*)d_in[6];
    const float* Wv = (const float*)d_in[7];
    const float* bv = (const float*)d_in[8];
    const float* Wo = (const float*)d_in[9];
    const float* bo = (const float*)d_in[10];
    float* out = (float*)d_out;

    float *qh, *kh, *vh, *ctx;
    cudaGetSymbolAddress((void**)&qh,  g_qh);
    cudaGetSymbolAddress((void**)&kh,  g_kh);
    cudaGetSymbolAddress((void**)&vh,  g_vh);
    cudaGetSymbolAddress((void**)&ctx, g_ctx);

    const int attn_smem = (4 * 64 * 68 + 3 * 64) * (int)sizeof(float); // ~70KB
    cudaFuncSetAttribute(gemm_tc_kernel,
                         cudaFuncAttributeMaxDynamicSharedMemorySize, GEMM_SMEM);
    cudaFuncSetAttribute(attn_kernel,
                         cudaFuncAttributeMaxDynamicSharedMemorySize, attn_smem);

    const dim3 gg(SIZE_ / 128, M_TOT / 128);   // (8, 32)
    const float qscale = 0.125f;               // 1/sqrt(HD)

    gemm_tc_kernel<<<gg, 256, GEMM_SMEM>>>(q, Wq, bq, qh, qscale);
    gemm_tc_kernel<<<gg, 256, GEMM_SMEM>>>(k, Wk, bk, kh, 1.0f);
    gemm_tc_kernel<<<gg, 256, GEMM_SMEM>>>(v, Wv, bv, vh, 1.0f);

    attn_kernel<<<dim3(SEQ / 64, HEADS, BATCH), 256, attn_smem>>>(qh, kh, vh, ctx);

    gemm_tc_kernel<<<gg, 256, GEMM_SMEM>>>(ctx, Wo, bo, out, 1.0f);
}

// round 8
// speedup vs baseline: 3.3577x; 2.0794x over previous
#include <cuda_runtime.h>
#include <cuda_bf16.h>
#include <cstdint>
#include <math.h>

#define SIZE_ 1024
#define HEADS 16
#define HD    64
#define SEQ   2048
#define BATCH 2
#define M_TOT (BATCH * SEQ)   // 4096

// Scratch (allocation-free)
__device__ float g_qh[M_TOT * SIZE_];
__device__ float g_kh[M_TOT * SIZE_];
__device__ float g_vh[M_TOT * SIZE_];
__device__ float g_ctx[M_TOT * SIZE_];

// ============================================================================
// Warp-level MMA helpers (base sm_103 ISA)
// ============================================================================
__device__ __forceinline__ uint32_t smem_u32(const void* p) {
    uint32_t a;
    asm("{ .reg .u64 t; cvta.to.shared.u64 t, %1; cvt.u32.u64 %0, t; }"
        : "=r"(a) : "l"(p));
    return a;
}
__device__ __forceinline__ void ldm_x4(uint32_t* r, uint32_t addr) {
    asm volatile("ldmatrix.sync.aligned.m8n8.x4.shared.b16 {%0,%1,%2,%3}, [%4];"
                 : "=r"(r[0]), "=r"(r[1]), "=r"(r[2]), "=r"(r[3]) : "r"(addr));
}
__device__ __forceinline__ void ldm_x4_t(uint32_t* r, uint32_t addr) {
    asm volatile("ldmatrix.sync.aligned.m8n8.x4.trans.shared.b16 {%0,%1,%2,%3}, [%4];"
                 : "=r"(r[0]), "=r"(r[1]), "=r"(r[2]), "=r"(r[3]) : "r"(addr));
}
__device__ __forceinline__ void mma_bf16(float* c, const uint32_t* a,
                                         const uint32_t* b) {
    asm volatile(
        "mma.sync.aligned.m16n8k16.row.col.f32.bf16.bf16.f32 "
        "{%0,%1,%2,%3}, {%4,%5,%6,%7}, {%8,%9}, {%0,%1,%2,%3};"
        : "+f"(c[0]), "+f"(c[1]), "+f"(c[2]), "+f"(c[3])
        : "r"(a[0]), "r"(a[1]), "r"(a[2]), "r"(a[3]), "r"(b[0]), "r"(b[1]));
}
__device__ __forceinline__ float ex2f(float x) {
    float y;
    asm("ex2.approx.f32 %0, %1;" : "=f"(y) : "f"(x));
    return y;
}
__device__ __forceinline__ void split4(float4 v, uint2& hi, uint2& lo) {
    __nv_bfloat162 h01 = __floats2bfloat162_rn(v.x, v.y);
    __nv_bfloat162 h23 = __floats2bfloat162_rn(v.z, v.w);
    __nv_bfloat162 l01 = __floats2bfloat162_rn(v.x - __low2float(h01),
                                               v.y - __high2float(h01));
    __nv_bfloat162 l23 = __floats2bfloat162_rn(v.z - __low2float(h23),
                                               v.w - __high2float(h23));
    hi.x = *(uint32_t*)&h01; hi.y = *(uint32_t*)&h23;
    lo.x = *(uint32_t*)&l01; lo.y = *(uint32_t*)&l23;
}
__device__ __forceinline__ void split2pack(float x, float y,
                                           uint32_t& hi, uint32_t& lo) {
    __nv_bfloat162 h = __floats2bfloat162_rn(x, y);
    __nv_bfloat162 l = __floats2bfloat162_rn(x - __low2float(h),
                                             y - __high2float(h));
    hi = *(uint32_t*)&h; lo = *(uint32_t*)&l;
}

// ============================================================================
// GEMM body (shared by fused-QKV and output projection kernels)
// C[m][n] = scale * (sum_k A[m][k]*W[n][k] + bias[n]); 3-term bf16 split.
// ============================================================================
#define KC 32
#define NCHUNK (SIZE_ / KC)            // 32
#define ASTR 40
#define TILEB (128 * ASTR * 2)         // 10240 B
#define GEMM_SMEM (2 * 4 * TILEB)      // 81920 B

__device__ __forceinline__
void gemm_body(const float* __restrict__ A, const float* __restrict__ W,
               const float* __restrict__ bias, float* __restrict__ C,
               float scale) {
    extern __shared__ char smem[];
    const uint32_t sb = smem_u32(smem);
    const int t = threadIdx.x, wid = t >> 5, lane = t & 31;
    const int m0 = blockIdx.y * 128, n0 = blockIdx.x * 128;
    const int wm = (wid >> 2) * 64;
    const int wn = (wid & 3) * 32;

    const int lr = lane & 7;
    const uint32_t aoff = (lr + ((lane >> 3) & 1) * 8) * ASTR + (lane >> 4) * 8;
    const uint32_t boff = (lr + (lane >> 4) * 8) * ASTR + ((lane >> 3) & 1) * 8;

    float acc[4][4][4] = {};
    float4 ga[4], gb[4];

    auto gload = [&](int chunk) {
        const int k0 = chunk * KC;
        #pragma unroll
        for (int e = 0; e < 4; e++) {
            int fi = e * 256 + t;
            int r = fi >> 3, c4 = fi & 7;
            ga[e] = *(const float4*)&A[(size_t)(m0 + r) * SIZE_ + k0 + c4 * 4];
            gb[e] = *(const float4*)&W[(size_t)(n0 + r) * SIZE_ + k0 + c4 * 4];
        }
    };
    auto cstore = [&](int buf) {
        char* base = smem + buf * 4 * TILEB;
        #pragma unroll
        for (int e = 0; e < 4; e++) {
            int fi = e * 256 + t;
            int r = fi >> 3, c4 = fi & 7;
            uint32_t off = (uint32_t)(r * ASTR + c4 * 4) * 2;
            uint2 hi, lo;
            split4(ga[e], hi, lo);
            *(uint2*)(base + off)             = hi;
            *(uint2*)(base + TILEB + off)     = lo;
            split4(gb[e], hi, lo);
            *(uint2*)(base + 2 * TILEB + off) = hi;
            *(uint2*)(base + 3 * TILEB + off) = lo;
        }
    };
    auto compute = [&](int buf) {
        const uint32_t AhiB = sb + buf * 4 * TILEB;
        const uint32_t AloB = AhiB + TILEB;
        const uint32_t BhiB = AhiB + 2 * TILEB;
        const uint32_t BloB = AhiB + 3 * TILEB;
        #pragma unroll
        for (int ks = 0; ks < KC; ks += 16) {
            uint32_t Ah[4][4], Al[4][4], Bh[8], Bl[8];
            #pragma unroll
            for (int mt = 0; mt < 4; mt++) {
                uint32_t o = 2u * (aoff + (wm + mt * 16) * ASTR + ks);
                ldm_x4(Ah[mt], AhiB + o);
                ldm_x4(Al[mt], AloB + o);
            }
            #pragma unroll
            for (int n2 = 0; n2 < 2; n2++) {
                uint32_t o = 2u * (boff + (wn + n2 * 16) * ASTR + ks);
                ldm_x4(&Bh[n2 * 4], BhiB + o);
                ldm_x4(&Bl[n2 * 4], BloB + o);
            }
            #pragma unroll
            for (int mt = 0; mt < 4; mt++)
                #pragma unroll
                for (int nt = 0; nt < 4; nt++) {
                    const uint32_t* bh = &Bh[(nt >> 1) * 4 + (nt & 1) * 2];
                    const uint32_t* bl = &Bl[(nt >> 1) * 4 + (nt & 1) * 2];
                    mma_bf16(acc[mt][nt], Ah[mt], bh);
                    mma_bf16(acc[mt][nt], Ah[mt], bl);
                    mma_bf16(acc[mt][nt], Al[mt], bh);
                }
        }
    };

    gload(0);
    cstore(0);
    for (int i = 0; i < NCHUNK; i++) {
        __syncthreads();
        if (i + 1 < NCHUNK) gload(i + 1);
        compute(i & 1);
        if (i + 1 < NCHUNK) cstore((i + 1) & 1);
    }

    const int gid = lane >> 2, tig = lane & 3;
    #pragma unroll
    for (int mt = 0; mt < 4; mt++) {
        #pragma unroll
        for (int nt = 0; nt < 4; nt++) {
            const int n = n0 + wn + nt * 8 + tig * 2;
            const int m = m0 + wm + mt * 16 + gid;
            float2 b01 = *(const float2*)&bias[n];
            float2 o0, o1;
            o0.x = scale * (acc[mt][nt][0] + b01.x);
            o0.y = scale * (acc[mt][nt][1] + b01.y);
            o1.x = scale * (acc[mt][nt][2] + b01.x);
            o1.y = scale * (acc[mt][nt][3] + b01.y);
            *(float2*)&C[(size_t)m * SIZE_ + n]       = o0;
            *(float2*)&C[(size_t)(m + 8) * SIZE_ + n] = o1;
        }
    }
}

// Q projection scale: (1/sqrt(64)) * log2(e), so softmax runs in base-2.
#define QSCALE 0.18033688011112042f

__global__ __launch_bounds__(256, 1)
void qkv_tc_kernel(const float* q, const float* k, const float* v,
                   const float* Wq, const float* bq,
                   const float* Wk, const float* bk,
                   const float* Wv, const float* bv,
                   float* oq, float* ok, float* ov) {
    const int z = blockIdx.z;
    const float* A    = z == 0 ? q  : (z == 1 ? k  : v);
    const float* W    = z == 0 ? Wq : (z == 1 ? Wk : Wv);
    const float* bias = z == 0 ? bq : (z == 1 ? bk : bv);
    float* C          = z == 0 ? oq : (z == 1 ? ok : ov);
    gemm_body(A, W, bias, C, z == 0 ? QSCALE : 1.0f);
}

__global__ __launch_bounds__(256, 1)
void gemm_tc_kernel(const float* __restrict__ A, const float* __restrict__ W,
                    const float* __restrict__ bias, float* __restrict__ C,
                    float scale) {
    gemm_body(A, W, bias, C, scale);
}

// ============================================================================
// Tensor-core flash attention.
// CTA = (128 queries, head, batch); 8 warps x 16 q-rows; KV tiles of 64.
// Scores = 3-term bf16 split QK^T (base-2 domain, scale pre-folded into Q).
// Softmax in registers; P split hi/lo packed directly into A-fragments.
// PV = 3-term split, V via ldmatrix.trans. All accumulation fp32.
// ============================================================================
#define KSTR 72
#define KTB  (64 * KSTR * 2)       // 9216 B per split tile
#define ATT_SMEM (4 * KTB)         // 36864 B (Kh|Kl|Vh|Vl; Q staging reuses)

__global__ __launch_bounds__(256, 2)
void attn_tc_kernel(const float* __restrict__ qg, const float* __restrict__ kg,
                    const float* __restrict__ vg, float* __restrict__ ctx) {
    extern __shared__ char smem[];
    const uint32_t sb = smem_u32(smem);
    const int t = threadIdx.x, wid = t >> 5, lane = t & 31;
    const int q0 = blockIdx.x * 128;
    const int h  = blockIdx.y;
    const int b  = blockIdx.z;
    const int g  = lane >> 2, qt = lane & 3;
    const int lr = lane & 7;

    const float* qbase = qg + (size_t)b * SEQ * SIZE_ + (size_t)h * HD;
    const float* kbase = kg + (size_t)b * SEQ * SIZE_ + (size_t)h * HD;
    const float* vbase = vg + (size_t)b * SEQ * SIZE_ + (size_t)h * HD;

    // ---- Stage Q (fp32 -> bf16 hi/lo) and grab persistent A-fragments ----
    // Qh at smem+0 (128 x KSTR bf16), Ql at +2*KTB.
    #pragma unroll
    for (int e = 0; e < 8; e++) {
        int fi = e * 256 + t;
        int r = fi >> 4, c4 = fi & 15;
        float4 v = *(const float4*)&qbase[(size_t)(q0 + r) * SIZE_ + c4 * 4];
        uint2 hi, lo;
        split4(v, hi, lo);
        uint32_t off = (uint32_t)(r * KSTR + c4 * 4) * 2;
        *(uint2*)(smem + off)           = hi;
        *(uint2*)(smem + 2 * KTB + off) = lo;
    }
    __syncthreads();

    const uint32_t aoff =
        (uint32_t)((lr + ((lane >> 3) & 1) * 8) * KSTR + (lane >> 4) * 8) * 2;
    const uint32_t boff =
        (uint32_t)((lr + (lane >> 4) * 8) * KSTR + ((lane >> 3) & 1) * 8) * 2;
    const uint32_t voff =
        (uint32_t)((lr + ((lane >> 3) & 1) * 8) * KSTR + (lane >> 4) * 8) * 2;

    uint32_t Qh[4][4], Ql[4][4];
    #pragma unroll
    for (int s = 0; s < 4; s++) {
        uint32_t o = aoff + (uint32_t)(wid * 16 * KSTR + s * 16) * 2;
        ldm_x4(Qh[s], sb + o);
        ldm_x4(Ql[s], sb + 2 * KTB + o);
    }
    __syncthreads();   // Q fragments in regs; smem free for K/V tiles

    float m0 = -1e30f, m1 = -1e30f, l0 = 0.f, l1 = 0.f;
    float O[8][4] = {};

    for (int kv0 = 0; kv0 < SEQ; kv0 += 64) {
        // ---- Load + split K,V tile into smem (Kh|Kl|Vh|Vl) ----
        float4 kv4[8];
        #pragma unroll
        for (int e = 0; e < 4; e++) {
            int fi = e * 256 + t;
            int r = fi >> 4, c4 = fi & 15;
            kv4[e]     = *(const float4*)&kbase[(size_t)(kv0 + r) * SIZE_ + c4 * 4];
            kv4[4 + e] = *(const float4*)&vbase[(size_t)(kv0 + r) * SIZE_ + c4 * 4];
        }
        __syncthreads();   // previous tile's smem reads done
        #pragma unroll
        for (int e = 0; e < 4; e++) {
            int fi = e * 256 + t;
            int r = fi >> 4, c4 = fi & 15;
            uint32_t off = (uint32_t)(r * KSTR + c4 * 4) * 2;
            uint2 hi, lo;
            split4(kv4[e], hi, lo);
            *(uint2*)(smem + off)           = hi;           // Kh
            *(uint2*)(smem + KTB + off)     = lo;           // Kl
            split4(kv4[4 + e], hi, lo);
            *(uint2*)(smem + 2 * KTB + off) = hi;           // Vh
            *(uint2*)(smem + 3 * KTB + off) = lo;           // Vl
        }
        __syncthreads();

        // ---- S = Q K^T (3-term split), 8 warps x (16 x 64) ----
        float S[8][4];
        #pragma unroll
        for (int np = 0; np < 4; np++) {
            #pragma unroll
            for (int i = 0; i < 4; i++) { S[2*np][i] = 0.f; S[2*np+1][i] = 0.f; }
            #pragma unroll
            for (int s = 0; s < 4; s++) {
                uint32_t bo = boff + (uint32_t)(np * 16 * KSTR + s * 16) * 2;
                uint32_t bh[4], bl[4];
                ldm_x4(bh, sb + bo);
                ldm_x4(bl, sb + KTB + bo);
                mma_bf16(S[2*np],   Qh[s], bh);
                mma_bf16(S[2*np],   Qh[s], bl);
                mma_bf16(S[2*np],   Ql[s], bh);
                mma_bf16(S[2*np+1], Qh[s], bh + 2);
                mma_bf16(S[2*np+1], Qh[s], bl + 2);
                mma_bf16(S[2*np+1], Ql[s], bh + 2);
            }
        }

        // ---- Online softmax in registers (base-2) ----
        float mx0 = -1e30f, mx1 = -1e30f;
        #pragma unroll
        for (int j = 0; j < 8; j++) {
            mx0 = fmaxf(mx0, fmaxf(S[j][0], S[j][1]));
            mx1 = fmaxf(mx1, fmaxf(S[j][2], S[j][3]));
        }
        mx0 = fmaxf(mx0, __shfl_xor_sync(0xffffffffu, mx0, 1));
        mx0 = fmaxf(mx0, __shfl_xor_sync(0xffffffffu, mx0, 2));
        mx1 = fmaxf(mx1, __shfl_xor_sync(0xffffffffu, mx1, 1));
        mx1 = fmaxf(mx1, __shfl_xor_sync(0xffffffffu, mx1, 2));
        float nm0 = fmaxf(m0, mx0), nm1 = fmaxf(m1, mx1);
        float sc0 = ex2f(m0 - nm0), sc1 = ex2f(m1 - nm1);
        m0 = nm0; m1 = nm1;

        float rs0 = 0.f, rs1 = 0.f;
        uint32_t Ph[4][4], Pl[4][4];
        #pragma unroll
        for (int sk = 0; sk < 4; sk++) {
            int j0 = 2 * sk, j1 = 2 * sk + 1;
            float p00 = ex2f(S[j0][0] - m0), p01 = ex2f(S[j0][1] - m0);
            float p02 = ex2f(S[j0][2] - m1), p03 = ex2f(S[j0][3] - m1);
            float p10 = ex2f(S[j1][0] - m0), p11 = ex2f(S[j1][1] - m0);
            float p12 = ex2f(S[j1][2] - m1), p13 = ex2f(S[j1][3] - m1);
            rs0 += p00 + p01 + p10 + p11;
            rs1 += p02 + p03 + p12 + p13;
            split2pack(p00, p01, Ph[sk][0], Pl[sk][0]);
            split2pack(p02, p03, Ph[sk][1], Pl[sk][1]);
            split2pack(p10, p11, Ph[sk][2], Pl[sk][2]);
            split2pack(p12, p13, Ph[sk][3], Pl[sk][3]);
        }
        rs0 += __shfl_xor_sync(0xffffffffu, rs0, 1);
        rs0 += __shfl_xor_sync(0xffffffffu, rs0, 2);
        rs1 += __shfl_xor_sync(0xffffffffu, rs1, 1);
        rs1 += __shfl_xor_sync(0xffffffffu, rs1, 2);
        l0 = l0 * sc0 + rs0;
        l1 = l1 * sc1 + rs1;
        #pragma unroll
        for (int db = 0; db < 8; db++) {
            O[db][0] *= sc0; O[db][1] *= sc0;
            O[db][2] *= sc1; O[db][3] *= sc1;
        }

        // ---- O += P V (3-term split), V via ldmatrix.trans ----
        #pragma unroll
        for (int np = 0; np < 4; np++) {
            #pragma unroll
            for (int sk = 0; sk < 4; sk++) {
                uint32_t vo = voff + (uint32_t)(sk * 16 * KSTR + np * 16) * 2;
                uint32_t vh[4], vl[4];
                ldm_x4_t(vh, sb + 2 * KTB + vo);
                ldm_x4_t(vl, sb + 3 * KTB + vo);
                mma_bf16(O[2*np],   Ph[sk], vh);
                mma_bf16(O[2*np],   Ph[sk], vl);
                mma_bf16(O[2*np],   Pl[sk], vh);
                mma_bf16(O[2*np+1], Ph[sk], vh + 2);
                mma_bf16(O[2*np+1], Ph[sk], vl + 2);
                mma_bf16(O[2*np+1], Pl[sk], vh + 2);
            }
        }
    }

    // ---- Normalize + write ctx [b][q][h*64+d] ----
    const float il0 = 1.0f / l0, il1 = 1.0f / l1;
    const int row0 = q0 + wid * 16 + g;
    float* cb = ctx + (size_t)b * SEQ * SIZE_ + (size_t)h * HD;
    #pragma unroll
    for (int db = 0; db < 8; db++) {
        const int col = db * 8 + qt * 2;
        float2 o0 = make_float2(O[db][0] * il0, O[db][1] * il0);
        float2 o1 = make_float2(O[db][2] * il1, O[db][3] * il1);
        *(float2*)&cb[(size_t)row0 * SIZE_ + col]       = o0;
        *(float2*)&cb[(size_t)(row0 + 8) * SIZE_ + col] = o1;
    }
}

// ----------------------------------------------------------------------------
// Host launch
// ----------------------------------------------------------------------------
extern "C" void kernel_launch(void* const* d_in, const int* in_sizes, int n_in,
                              void* d_out, int out_size) {
    const float* q  = (const float*)d_in[0];
    const float* k  = (const float*)d_in[1];
    const float* v  = (const float*)d_in[2];
    const float* Wq = (const float*)d_in[3];
    const float* bq = (const float*)d_in[4];
    const float* Wk = (const float*)d_in[5];
    const float* bk = (const float*)d_in[6];
    const float* Wv = (const float*)d_in[7];
    const float* bv = (const float*)d_in[8];
    const float* Wo = (const float*)d_in[9];
    const float* bo = (const float*)d_in[10];
    float* out = (float*)d_out;

    float *qh, *kh, *vh, *ctx;
    cudaGetSymbolAddress((void**)&qh,  g_qh);
    cudaGetSymbolAddress((void**)&kh,  g_kh);
    cudaGetSymbolAddress((void**)&vh,  g_vh);
    cudaGetSymbolAddress((void**)&ctx, g_ctx);

    cudaFuncSetAttribute(qkv_tc_kernel,
                         cudaFuncAttributeMaxDynamicSharedMemorySize, GEMM_SMEM);
    cudaFuncSetAttribute(gemm_tc_kernel,
                         cudaFuncAttributeMaxDynamicSharedMemorySize, GEMM_SMEM);
    cudaFuncSetAttribute(attn_tc_kernel,
                         cudaFuncAttributeMaxDynamicSharedMemorySize, ATT_SMEM);

    qkv_tc_kernel<<<dim3(8, 32, 3), 256, GEMM_SMEM>>>(
        q, k, v, Wq, bq, Wk, bk, Wv, bv, qh, kh, vh);

    attn_tc_kernel<<<dim3(SEQ / 128, HEADS, BATCH), 256, ATT_SMEM>>>(
        qh, kh, vh, ctx);

    gemm_tc_kernel<<<dim3(8, 32), 256, GEMM_SMEM>>>(ctx, Wo, bo, out, 1.0f);
}